// round 17
// baseline (speedup 1.0000x reference)
#include <cuda_runtime.h>
#include <cuda_bf16.h>
#include <cstdint>
#include <cstddef>

// Problem constants
#define BATCH 2
#define NPTS  40000
#define KNN   16
#define CIN   64
#define CADD  3
#define CTOT  67
#define MDIM  16
#define FDIM  1072            // CTOT*MDIM
#define FDIMP 1088            // padded feature count (rows are 1088 B in int8)
#define COUT  128
#define TOTPTS (BATCH * NPTS) // 80000

// int8 GEMM tiling: block 64 rows x 128 cols, 8 warps (4M x 2N, warp 16x64)
#define GBM    64
#define CHB    64             // K bytes per chunk
#define NCHQ   17             // 1088 / 64
#define NSTG   3
#define A_TILE 4096           // 64 rows x 64 B
#define B_TILE 8192           // 128 rows x 64 B
#define STAGE_Q (2 * A_TILE + 2 * B_TILE)   // 24576 B (Ah, Al, Bh, Bl)
#define SMEM_Q  (NSTG * STAGE_Q)            // 73728 B -> 2 blocks/SM

// ---------------------------------------------------------------------------
// Device-global scratch (no runtime allocation allowed)
// ---------------------------------------------------------------------------
__device__ uint8_t g_Pqh[(size_t)TOTPTS * FDIMP];   // 87 MB  (hi bytes)
__device__ uint8_t g_Pql[(size_t)TOTPTS * FDIMP];   // 87 MB  (lo bytes)
__device__ uint8_t g_Wqh[COUT * FDIMP];
__device__ uint8_t g_Wql[COUT * FDIMP];
__device__ float   g_sA[TOTPTS];
__device__ float   g_sB[COUT];
__device__ int     g_is64;

// ---------------------------------------------------------------------------
// PTX helpers (base sm_103 target — tcgen05 is NOT available, per R3)
// ---------------------------------------------------------------------------
__device__ __forceinline__ uint32_t smem_u32(const void* p) {
    uint32_t a;
    asm("{ .reg .u64 t; cvta.to.shared.u64 t, %1; cvt.u32.u64 %0, t; }" : "=r"(a) : "l"(p));
    return a;
}
__device__ __forceinline__ void cpasync16(uint32_t dst, const void* src) {
    asm volatile("cp.async.cg.shared.global [%0], [%1], 16;" :: "r"(dst), "l"(src));
}
#define CP_COMMIT() asm volatile("cp.async.commit_group;" ::: "memory")
#define CP_WAIT2()  asm volatile("cp.async.wait_group 2;" ::: "memory")

__device__ __forceinline__ void ldsm4(uint32_t* r, uint32_t addr) {
    asm volatile("ldmatrix.sync.aligned.m8n8.x4.shared.b16 {%0,%1,%2,%3}, [%4];"
                 : "=r"(r[0]), "=r"(r[1]), "=r"(r[2]), "=r"(r[3]) : "r"(addr));
}
// s8 MMA, s32 accumulate: exact integer arithmetic.
__device__ __forceinline__ void mma_s8(int* d, const uint32_t* a, const uint32_t* b) {
    asm volatile("mma.sync.aligned.m16n8k32.row.col.s32.s8.s8.s32 "
                 "{%0,%1,%2,%3}, {%4,%5,%6,%7}, {%8,%9}, {%0,%1,%2,%3};"
                 : "+r"(d[0]), "+r"(d[1]), "+r"(d[2]), "+r"(d[3])
                 : "r"(a[0]), "r"(a[1]), "r"(a[2]), "r"(a[3]), "r"(b[0]), "r"(b[1]));
}

// XOR swizzle for 64B rows: logical 16B chunk c -> physical c ^ ((row>>1)&3).
__device__ __forceinline__ uint32_t sw_off(uint32_t row, uint32_t c) {
    return row * 64 + ((c ^ ((row >> 1) & 3)) << 4);
}

// Packed fp32 pair FMA (R15, banked): bit-identical to two scalar FFMAs.
__device__ __forceinline__ void fma_f32x2(unsigned long long& acc,
                                          unsigned long long w,
                                          unsigned long long f) {
    asm("fma.rn.f32x2 %0, %1, %2, %0;" : "+l"(acc) : "l"(w), "l"(f));
}

// Quantize v (units of s) -> hi, lo int8 with q = 128*hi + lo, |q| <= 16256.
__device__ __forceinline__ void quant2(float q, int& hi, int& lo) {
    hi = __float2int_rn(q * 0.0078125f);            // q / 128
    lo = __float2int_rn(fmaf(-128.f, (float)hi, q));
}

// ---------------------------------------------------------------------------
// Index dtype detection (i64 vs i32 neighbor_inds)
// ---------------------------------------------------------------------------
__global__ void detect_kernel(const void* __restrict__ idx) {
    const unsigned* p = (const unsigned*)idx;
    int is64 = 1;
    for (int i = 0; i < 64; ++i)
        if (p[2 * i + 1] != 0u) { is64 = 0; break; }
    g_is64 = is64;
}

// ---------------------------------------------------------------------------
// Weight quantize: W[128,1072] fp32 -> int8 hi/lo [128,1088] + per-row scale.
// One block per output row.
// ---------------------------------------------------------------------------
__global__ void __launch_bounds__(128) wquant_kernel(const float* __restrict__ W) {
    __shared__ float red[128];
    __shared__ float s_inv;
    const int row = blockIdx.x;
    const int tid = threadIdx.x;

    float mx = 0.f;
    for (int c = tid; c < FDIM; c += 128)
        mx = fmaxf(mx, fabsf(W[row * FDIM + c]));
    red[tid] = mx;
    __syncthreads();
    if (tid < 32) {
        float m = fmaxf(fmaxf(red[tid], red[tid + 32]),
                        fmaxf(red[tid + 64], red[tid + 96]));
        #pragma unroll
        for (int o = 16; o > 0; o >>= 1)
            m = fmaxf(m, __shfl_xor_sync(0xFFFFFFFFu, m, o));
        if (tid == 0) {
            s_inv = (m > 0.f) ? (16256.f / m) : 0.f;
            g_sB[row] = m * (1.f / 16256.f);
        }
    }
    __syncthreads();
    const float inv = s_inv;

    if (tid < FDIMP / 16) {              // 68 threads, 16 bytes each
        unsigned wh[4], wl[4];
        #pragma unroll
        for (int g = 0; g < 4; ++g) {
            unsigned ph = 0, pl = 0;
            #pragma unroll
            for (int i = 0; i < 4; ++i) {
                int c = tid * 16 + g * 4 + i;
                float v = (c < FDIM) ? W[row * FDIM + c] : 0.f;
                int hi, lo; quant2(v * inv, hi, lo);
                ph |= ((unsigned)hi & 0xFFu) << (8 * i);
                pl |= ((unsigned)lo & 0xFFu) << (8 * i);
            }
            wh[g] = ph; wl[g] = pl;
        }
        *(uint4*)(g_Wqh + (size_t)row * FDIMP + tid * 16) = make_uint4(wh[0], wh[1], wh[2], wh[3]);
        *(uint4*)(g_Wql + (size_t)row * FDIMP + tid * 16) = make_uint4(wl[0], wl[1], wl[2], wl[3]);
    }
}

// ---------------------------------------------------------------------------
// Kernel 1: per-point PConv -> int8 hi/lo split + per-point scale.
// R15 f32x2 accumulation body (banked); emit: block max -> dual-word quantize.
// ---------------------------------------------------------------------------
__global__ void __launch_bounds__(128, 12) pconv_kernel(
    const float* __restrict__ in_feat,
    const void*  __restrict__ idx,       // neighbor_inds, i64 or i32
    const float* __restrict__ wn,
    const float* __restrict__ addf)
{
    __shared__ float feats[KNN][68];
    __shared__ __align__(16) float wns[KNN][MDIM];
    __shared__ int   nb[KNN];
    __shared__ float red[128];
    __shared__ float s_inv, s_scale;

    const int point = blockIdx.x;
    const int b     = point / NPTS;
    const int tid   = threadIdx.x;

    if (tid < KNN) {
        int v;
        if (g_is64) v = (int)((const long long*)idx)[(size_t)point * KNN + tid];
        else        v = ((const int*)idx)[(size_t)point * KNN + tid];
        nb[tid] = v;
    }
    if (tid < 64) {
        float4 w = ((const float4*)wn)[(size_t)point * 64 + tid];
        ((float4*)&wns[0][0])[tid] = w;
    }
    if (tid < KNN * CADD) {
        int k = tid / CADD, a = tid - k * CADD;
        feats[k][CIN + a] = addf[(size_t)point * (KNN * CADD) + tid];
    }
    __syncthreads();

    #pragma unroll
    for (int i = tid; i < KNN * 16; i += 128) {
        int k = i >> 4, q = i & 15;
        float4 v = ((const float4*)in_feat)[((size_t)b * NPTS + nb[k]) * 16 + q];
        *((float4*)&feats[k][q * 4]) = v;
    }
    __syncthreads();

    float acc[16];
    float mx = 0.f;
    if (tid < CTOT) {
        const uint32_t wbase = smem_u32(&wns[0][0]);
        unsigned long long acc2[8];
        #pragma unroll
        for (int j = 0; j < 8; ++j) acc2[j] = 0ull;

        #pragma unroll
        for (int k = 0; k < KNN; ++k) {
            float f = feats[k][tid];
            unsigned long long ff;
            asm("mov.b64 %0, {%1, %1};" : "=l"(ff) : "f"(f));
            unsigned long long w0, w1, w2, w3, w4, w5, w6, w7;
            asm volatile("ld.shared.v2.u64 {%0, %1}, [%2];"
                         : "=l"(w0), "=l"(w1) : "r"(wbase + k * 64));
            asm volatile("ld.shared.v2.u64 {%0, %1}, [%2];"
                         : "=l"(w2), "=l"(w3) : "r"(wbase + k * 64 + 16));
            asm volatile("ld.shared.v2.u64 {%0, %1}, [%2];"
                         : "=l"(w4), "=l"(w5) : "r"(wbase + k * 64 + 32));
            asm volatile("ld.shared.v2.u64 {%0, %1}, [%2];"
                         : "=l"(w6), "=l"(w7) : "r"(wbase + k * 64 + 48));
            fma_f32x2(acc2[0], w0, ff);
            fma_f32x2(acc2[1], w1, ff);
            fma_f32x2(acc2[2], w2, ff);
            fma_f32x2(acc2[3], w3, ff);
            fma_f32x2(acc2[4], w4, ff);
            fma_f32x2(acc2[5], w5, ff);
            fma_f32x2(acc2[6], w6, ff);
            fma_f32x2(acc2[7], w7, ff);
        }
        #pragma unroll
        for (int j = 0; j < 8; ++j) {
            uint32_t lo, hi;
            asm("mov.b64 {%0, %1}, %2;" : "=r"(lo), "=r"(hi) : "l"(acc2[j]));
            acc[2 * j]     = __uint_as_float(lo);
            acc[2 * j + 1] = __uint_as_float(hi);
        }
        #pragma unroll
        for (int i = 0; i < 16; ++i) mx = fmaxf(mx, fabsf(acc[i]));
    }

    // block max-reduce over the 67 active channels
    red[tid] = mx;
    __syncthreads();
    if (tid < 32) {
        float m = fmaxf(fmaxf(red[tid], red[tid + 32]),
                        fmaxf(red[tid + 64], red[tid + 96]));
        #pragma unroll
        for (int o = 16; o > 0; o >>= 1)
            m = fmaxf(m, __shfl_xor_sync(0xFFFFFFFFu, m, o));
        if (tid == 0) {
            s_inv   = (m > 0.f) ? (16256.f / m) : 0.f;
            s_scale = m * (1.f / 16256.f);
        }
    }
    __syncthreads();

    if (tid < CTOT) {
        const float inv = s_inv;
        unsigned ph[4], pl[4];
        #pragma unroll
        for (int g = 0; g < 4; ++g) {
            unsigned wh = 0, wl = 0;
            #pragma unroll
            for (int i = 0; i < 4; ++i) {
                int hi, lo; quant2(acc[g * 4 + i] * inv, hi, lo);
                wh |= ((unsigned)hi & 0xFFu) << (8 * i);
                wl |= ((unsigned)lo & 0xFFu) << (8 * i);
            }
            ph[g] = wh; pl[g] = wl;
        }
        const size_t off = (size_t)point * FDIMP + tid * 16;
        *(uint4*)(g_Pqh + off) = make_uint4(ph[0], ph[1], ph[2], ph[3]);
        *(uint4*)(g_Pql + off) = make_uint4(pl[0], pl[1], pl[2], pl[3]);
    }
    if (tid == 0) g_sA[point] = s_scale;
    if (tid == 67) {   // zero K-pad [1072, 1088)
        uint4 z = make_uint4(0, 0, 0, 0);
        *(uint4*)(g_Pqh + (size_t)point * FDIMP + FDIM) = z;
        *(uint4*)(g_Pql + (size_t)point * FDIMP + FDIM) = z;
    }
}

// ---------------------------------------------------------------------------
// Kernel 2: int8 dual-word GEMM.  out[80000x128] = P * W^T + bias.
// 1250 blocks x (M=64, N=128), 256 threads (8 warps, warp tile 16x64),
// 3-stage cp.async pipeline, XOR-swizzled 64B rows, 2 blocks/SM.
// q = 128*hi + lo; out = sA*sB*(16384*HH + 128*(HL+LH)) + bias (LL dropped).
// ---------------------------------------------------------------------------
__global__ void __launch_bounds__(256, 2)
gemm_q_kernel(const float* __restrict__ bias, float* __restrict__ out)
{
    extern __shared__ char dsm[];
    __shared__ float bias_s[COUT];
    __shared__ float sBs[COUT];
    __shared__ float sAs[GBM];

    const int tid  = threadIdx.x;
    const int lane = tid & 31;
    const int wid  = tid >> 5;
    const int wm   = wid & 3;            // 4 warps along M (16 rows each)
    const int wn   = wid >> 2;           // 2 warps along N (64 cols each)
    const size_t rowBase = (size_t)blockIdx.x * GBM;
    const uint32_t tb = smem_u32(dsm);

    if (tid < COUT) { bias_s[tid] = bias[tid]; sBs[tid] = g_sB[tid]; }
    if (tid < GBM)  sAs[tid] = g_sA[rowBase + tid];

    const uint8_t* srcA[2] = { g_Pqh + rowBase * FDIMP, g_Pql + rowBase * FDIMP };
    const uint8_t* srcB[2] = { g_Wqh, g_Wql };

    // per-stage copy: 1536 x 16B chunks, 6 per thread
    auto load_chunk = [&](int chunk, int s) {
        const uint32_t st = tb + s * STAGE_Q;
        const size_t coff = (size_t)chunk * CHB;
        #pragma unroll
        for (int i = 0; i < 6; ++i) {
            int j = tid + i * 256;              // 0..1535
            if (j < 512) {                      // A tiles (hi, lo)
                int set = j >> 8, idx = j & 255;
                int row = idx >> 2, c = idx & 3;
                cpasync16(st + set * A_TILE + sw_off(row, c),
                          srcA[set] + (size_t)row * FDIMP + coff + c * 16);
            } else {                            // B tiles (hi, lo)
                int jb = j - 512;
                int set = jb >> 9, idx = jb & 511;
                int row = idx >> 2, c = idx & 3;
                cpasync16(st + 2 * A_TILE + set * B_TILE + sw_off(row, c),
                          srcB[set] + (size_t)row * FDIMP + coff + c * 16);
            }
        }
    };

    int acc_hh[8][4], acc_m[8][4];
    #pragma unroll
    for (int nt = 0; nt < 8; ++nt)
        #pragma unroll
        for (int r = 0; r < 4; ++r) { acc_hh[nt][r] = 0; acc_m[nt][r] = 0; }

    // ldmatrix logical coordinates
    const uint32_t a_row0 = (uint32_t)(wm * 16 + (lane & 15));
    const uint32_t a_c0   = (uint32_t)(lane >> 4);            // + k32*2
    const uint32_t b_row0 = (uint32_t)(wn * 64 + ((lane >> 4) << 3) + (lane & 7));
    const uint32_t b_c0   = (uint32_t)((lane >> 3) & 1);      // + k32*2

    load_chunk(0, 0); CP_COMMIT();
    load_chunk(1, 1); CP_COMMIT();

    for (int t = 0; t < NCHQ; ++t) {
        const int s = t % NSTG;
        if (t + 2 < NCHQ) load_chunk(t + 2, (t + 2) % NSTG);
        CP_COMMIT();
        CP_WAIT2();
        __syncthreads();

        const uint32_t st = tb + s * STAGE_Q;

        #pragma unroll
        for (int k32 = 0; k32 < 2; ++k32) {
            uint32_t a_h[4], a_l[4];
            const uint32_t aoff = sw_off(a_row0, a_c0 + k32 * 2);
            ldsm4(a_h, st + aoff);
            ldsm4(a_l, st + A_TILE + aoff);

            #pragma unroll
            for (int nt2 = 0; nt2 < 4; ++nt2) {
                const uint32_t boff = sw_off(b_row0 + nt2 * 16, b_c0 + k32 * 2);
                uint32_t rh[4], rl[4];
                ldsm4(rh, st + 2 * A_TILE + boff);
                ldsm4(rl, st + 2 * A_TILE + B_TILE + boff);
                uint32_t bh0[2] = { rh[0], rh[1] }, bh1[2] = { rh[2], rh[3] };
                uint32_t bl0[2] = { rl[0], rl[1] }, bl1[2] = { rl[2], rl[3] };
                mma_s8(acc_hh[nt2 * 2],     a_h, bh0);
                mma_s8(acc_m [nt2 * 2],     a_h, bl0);
                mma_s8(acc_m [nt2 * 2],     a_l, bh0);
                mma_s8(acc_hh[nt2 * 2 + 1], a_h, bh1);
                mma_s8(acc_m [nt2 * 2 + 1], a_h, bl1);
                mma_s8(acc_m [nt2 * 2 + 1], a_l, bh1);
            }
        }
        __syncthreads();
    }

    // epilogue: rescale + bias + store (float2 per fragment half-row)
    const int r_in = wm * 16 + (lane >> 2);
    const float fA0 = sAs[r_in], fA1 = sAs[r_in + 8];
    const size_t r0 = rowBase + r_in;

    #pragma unroll
    for (int nt = 0; nt < 8; ++nt) {
        const int col = wn * 64 + nt * 8 + (lane & 3) * 2;
        const float sb0 = sBs[col], sb1 = sBs[col + 1];
        const float b0 = bias_s[col], b1 = bias_s[col + 1];
        float v00 = fmaf((float)acc_hh[nt][0], 16384.f, (float)acc_m[nt][0] * 128.f);
        float v01 = fmaf((float)acc_hh[nt][1], 16384.f, (float)acc_m[nt][1] * 128.f);
        float v10 = fmaf((float)acc_hh[nt][2], 16384.f, (float)acc_m[nt][2] * 128.f);
        float v11 = fmaf((float)acc_hh[nt][3], 16384.f, (float)acc_m[nt][3] * 128.f);
        *(float2*)(out + r0 * COUT + col) =
            make_float2(fmaf(v00, fA0 * sb0, b0), fmaf(v01, fA0 * sb1, b1));
        *(float2*)(out + (r0 + 8) * COUT + col) =
            make_float2(fmaf(v10, fA1 * sb0, b0), fmaf(v11, fA1 * sb1, b1));
    }
}

// ---------------------------------------------------------------------------
// Launch
// ---------------------------------------------------------------------------
extern "C" void kernel_launch(void* const* d_in, const int* in_sizes, int n_in,
                              void* d_out, int out_size)
{
    const float* in_feat = (const float*)d_in[0];
    const void*  ninds   = d_in[1];
    const float* wn      = (const float*)d_in[5];
    const float* addf    = (const float*)d_in[6];
    const float* W       = (const float*)d_in[7];
    const float* bias    = (const float*)d_in[8];
    float*       out     = (float*)d_out;

    cudaFuncSetAttribute(gemm_q_kernel,
                         cudaFuncAttributeMaxDynamicSharedMemorySize, SMEM_Q);

    detect_kernel<<<1, 1>>>(ninds);
    wquant_kernel<<<COUT, 128>>>(W);
    pconv_kernel<<<TOTPTS, 128>>>(in_feat, ninds, wn, addf);
    gemm_q_kernel<<<TOTPTS / GBM, 256, SMEM_Q>>>(bias, out);
}